// round 10
// baseline (speedup 1.0000x reference)
#include <cuda_runtime.h>
#include <cstdint>
#include <math.h>

#define BB 8
#define CC 256
#define HH 96
#define WW 128
#define HWSZ (HH*WW)
#define RD 4
#define ND 9
#define TILE_H 8
#define TILE_W 32
#define NTHREADS 288          // 4 g(8px) * 8 ty * 9 dy
#define CHUNK 8
#define NCHUNK 32
#define NBUF 4

#define FQ_PITCH 44           // floats per fq halo row (40 used), conflict-free
#define FR_PITCH 36           // floats per fr row (32 used), conflict-free
#define FQ_STG (CHUNK*16*FQ_PITCH)   // 5632 floats per buffer
#define FR_STG (CHUNK*8*FR_PITCH)    // 2304 floats per buffer
#define FQ_F (NBUF*FQ_STG)           // 22528
#define FR_F (NBUF*FR_STG)           // 9216
#define FRN_F 256
#define FQN_F 704
#define SMEM_FLOATS (FQ_F + FR_F + FRN_F + FQN_F)
#define SMEM_BYTES  (SMEM_FLOATS * 4)

#define FQ_SLOTS 1280
#define TOT_SLOTS 1792
#define NSLOT_IT 7

__device__ __forceinline__ void cpasync16(unsigned sa, const float* src) {
    asm volatile("cp.async.cg.shared.global [%0], [%1], 16;\n" :: "r"(sa), "l"(src));
}
__device__ __forceinline__ unsigned smem_u32(const void* p) {
    return (unsigned)__cvta_generic_to_shared(p);
}

#define STAGE(BUFL) do {                                                    \
    _Pragma("unroll")                                                       \
    for (int it = 0; it < NSLOT_IT; ++it) {                                 \
        if (val[it]) cpasync16(dst[it] + (BUFL) * dlt[it], src[it]);        \
        src[it] += (size_t)CHUNK * HWSZ;                                    \
    }                                                                       \
    asm volatile("cp.async.commit_group;\n");                               \
} while (0)

// load channel CH operands into register slot SL (prefetchable)
#define LOADCH(CH, SL) do {                                                 \
    const float* fqc_ = sfqb_ + (CH) * (16*FQ_PITCH);                       \
    const float* frc_ = sfrb_ + (CH) * (8*FR_PITCH);                        \
    *(float4*)&fbuf[SL][0] = *(const float4*)(frc_ + foff);                 \
    *(float4*)&fbuf[SL][4] = *(const float4*)(frc_ + foff + 4);             \
    const float* rp_ = fqc_ + qoff;                                         \
    *(float4*)&qbuf[SL][0]  = *(const float4*)(rp_);                        \
    *(float4*)&qbuf[SL][4]  = *(const float4*)(rp_ + 4);                    \
    *(float4*)&qbuf[SL][8]  = *(const float4*)(rp_ + 8);                    \
    *(float4*)&qbuf[SL][12] = *(const float4*)(rp_ + 12);                   \
    nq0[SL] = fqc_[o0];                                                     \
    nq1[SL] = fqc_[o1];                                                     \
    if (tid < 64) nq2[SL] = fqc_[o2];                                       \
} while (0)

#define COMP(BUFL) do {                                                     \
    const float* sfqb_ = sm + (BUFL) * FQ_STG;                              \
    const float* sfrb_ = sm + FQ_F + (BUFL) * FR_STG;                       \
    float qbuf[2][16], fbuf[2][8];                                          \
    float nq0[2], nq1[2], nq2[2];                                           \
    nq2[0] = 0.f; nq2[1] = 0.f;                                             \
    LOADCH(0, 0);                                                           \
    _Pragma("unroll")                                                       \
    for (int ch = 0; ch < CHUNK; ++ch) {                                    \
        const int cur = ch & 1;                                             \
        if (ch + 1 < CHUNK) LOADCH(ch + 1, cur ^ 1);                        \
        fqs0 = fmaf(nq0[cur], nq0[cur], fqs0);                              \
        fqs1 = fmaf(nq1[cur], nq1[cur], fqs1);                              \
        if (tid < 64) fqs2 = fmaf(nq2[cur], nq2[cur], fqs2);                \
        if (dy == RD) {                                                     \
            _Pragma("unroll")                                               \
            for (int i = 0; i < 8; ++i)                                     \
                frs[i] = fmaf(fbuf[cur][i], fbuf[cur][i], frs[i]);          \
        }                                                                   \
        _Pragma("unroll")                                                   \
        for (int i = 0; i < 8; ++i)                                         \
            _Pragma("unroll")                                               \
            for (int dx = 0; dx < ND; ++dx)                                 \
                acc[i*ND + dx] = fmaf(fbuf[cur][i], qbuf[cur][i + dx],      \
                                      acc[i*ND + dx]);                      \
    }                                                                       \
} while (0)

#define ITER(K, SB, CB) do {                                                \
    if ((K) + 2 < NCHUNK) { STAGE(SB); }                                    \
    else { asm volatile("cp.async.commit_group;\n"); }                      \
    asm volatile("cp.async.wait_group 2;\n");                               \
    __syncthreads();                                                        \
    COMP(CB);                                                               \
} while (0)

__global__ __launch_bounds__(NTHREADS, 1)
void corr_kernel(const float* __restrict__ fr, const float* __restrict__ fq,
                 float* __restrict__ out) {
    extern __shared__ float sm[];
    float* s_fq  = sm;
    float* s_fr  = sm + FQ_F;
    float* s_frn = sm + FQ_F + FR_F;
    float* s_fqn = s_frn + FRN_F;

    const int b  = blockIdx.z;
    const int h0 = blockIdx.y * TILE_H;
    const int w0 = blockIdx.x * TILE_W;
    const int tid = threadIdx.x;
    const int g  = tid & 3;           // 8-px group
    const int ty = (tid >> 2) & 7;
    const int dy = tid >> 5;          // warp-uniform, 0..8

    const float* frb = fr + (size_t)b * CC * HWSZ;
    const float* fqb = fq + (size_t)b * CC * HWSZ;

    const int foff = ty * FR_PITCH + 8 * g;
    const int qoff = (ty + dy) * FQ_PITCH + 8 * g;

    // fq-norm halo positions (16x40 = 640): tid, tid+288, tid+576(tid<64)
    const int o0 = (tid / 40) * FQ_PITCH + (tid % 40);
    const int p1 = tid + NTHREADS;
    const int o1 = (p1 / 40) * FQ_PITCH + (p1 % 40);
    const int p2 = tid + 2 * NTHREADS;
    const int o2 = (p2 / 40) * FQ_PITCH + (p2 % 40);

    // ---- precompute staging slots ----
    const float* src[NSLOT_IT];
    unsigned dst[NSLOT_IT], dlt[NSLOT_IT];
    bool val[NSLOT_IT];
    #pragma unroll
    for (int it = 0; it < NSLOT_IT; ++it) {
        int idx = tid + it * NTHREADS;
        val[it] = false; src[it] = frb; dst[it] = smem_u32(sm); dlt[it] = 0;
        if (idx < FQ_SLOTS) {
            int ch  = idx / 160;
            int rem = idx - ch * 160;
            int row = rem / 10;
            int c16 = rem - row * 10;
            int hg = h0 + row - RD;
            int wg = w0 + c16 * 4 - RD;
            bool v = (hg >= 0 && hg < HH && wg >= 0 && wg <= WW - 4);
            val[it] = v;
            dst[it] = smem_u32(s_fq + (ch * 16 + row) * FQ_PITCH + c16 * 4);
            dlt[it] = FQ_STG * 4;
            if (v) src[it] = fqb + (size_t)ch * HWSZ + hg * WW + wg;
        } else if (idx < TOT_SLOTS) {
            int j   = idx - FQ_SLOTS;
            int ch  = j >> 6;
            int rem = j & 63;
            int row = rem >> 3;
            int c16 = rem & 7;
            val[it] = true;
            dst[it] = smem_u32(s_fr + (ch * 8 + row) * FR_PITCH + c16 * 4);
            dlt[it] = FR_STG * 4;
            src[it] = frb + (size_t)ch * HWSZ + (h0 + row) * WW + (w0 + c16 * 4);
        }
    }

    // zero fq buffers once (OOB halo + pad cols never overwritten by cp.async)
    for (int i = tid; i < FQ_F; i += NTHREADS) s_fq[i] = 0.f;
    __syncthreads();

    float acc[72];
    #pragma unroll
    for (int i = 0; i < 72; ++i) acc[i] = 0.f;
    float frs[8] = {0,0,0,0,0,0,0,0};
    float fqs0 = 0.f, fqs1 = 0.f, fqs2 = 0.f;

    STAGE(0);
    STAGE(1);

    #pragma unroll 1
    for (int kb = 0; kb < NCHUNK / 4; ++kb) {
        const int k0 = kb * 4;
        ITER(k0 + 0, 2, 0);
        ITER(k0 + 1, 3, 1);
        ITER(k0 + 2, 0, 2);
        ITER(k0 + 3, 1, 3);
    }

    // ---- exchange inverse norms through smem ----
    if (dy == RD) {
        #pragma unroll
        for (int i = 0; i < 8; ++i)
            s_frn[ty * TILE_W + 8 * g + i] = 1.0f / fmaxf(sqrtf(frs[i]), 1e-12f);
    }
    s_fqn[o0] = 1.0f / fmaxf(sqrtf(fqs0), 1e-12f);
    s_fqn[o1] = 1.0f / fmaxf(sqrtf(fqs1), 1e-12f);
    if (tid < 64)
        s_fqn[o2] = 1.0f / fmaxf(sqrtf(fqs2), 1e-12f);
    __syncthreads();

    const int h = h0 + ty;
    const int w_base = w0 + 8 * g;

    float invfr[8];
    #pragma unroll
    for (int i = 0; i < 8; ++i)
        invfr[i] = s_frn[ty * TILE_W + 8 * g + i];

    float invq[16];
    #pragma unroll
    for (int j = 0; j < 16; ++j)
        invq[j] = s_fqn[(ty + dy) * FQ_PITCH + 8 * g + j];

    const float scale = 1.0f / (float)CC;
    #pragma unroll
    for (int dx = 0; dx < ND; ++dx) {
        float4 oA, oB;
        oA.x = acc[0*ND + dx] * invfr[0] * invq[0 + dx] * scale;
        oA.y = acc[1*ND + dx] * invfr[1] * invq[1 + dx] * scale;
        oA.z = acc[2*ND + dx] * invfr[2] * invq[2 + dx] * scale;
        oA.w = acc[3*ND + dx] * invfr[3] * invq[3 + dx] * scale;
        oB.x = acc[4*ND + dx] * invfr[4] * invq[4 + dx] * scale;
        oB.y = acc[5*ND + dx] * invfr[5] * invq[5 + dx] * scale;
        oB.z = acc[6*ND + dx] * invfr[6] * invq[6 + dx] * scale;
        oB.w = acc[7*ND + dx] * invfr[7] * invq[7 + dx] * scale;
        size_t off = (((size_t)b * (ND*ND) + (size_t)(dy*ND + dx)) * HH + h) * WW + w_base;
        *(float4*)&out[off]     = oA;
        *(float4*)&out[off + 4] = oB;
    }
}

extern "C" void kernel_launch(void* const* d_in, const int* in_sizes, int n_in,
                              void* d_out, int out_size) {
    const float* fr = (const float*)d_in[0];
    const float* fq = (const float*)d_in[1];
    float* out = (float*)d_out;
    (void)in_sizes; (void)n_in; (void)out_size;

    cudaFuncSetAttribute(corr_kernel, cudaFuncAttributeMaxDynamicSharedMemorySize, SMEM_BYTES);

    dim3 grid(WW / TILE_W, HH / TILE_H, BB);   // (4, 12, 8) = 384 CTAs
    corr_kernel<<<grid, NTHREADS, SMEM_BYTES>>>(fr, fq, out);
}